// round 5
// baseline (speedup 1.0000x reference)
#include <cuda_runtime.h>
#include <math.h>

#define B_    256
#define N_    1152
#define C_    10
#define IN_   8
#define KO_   160
#define NG_   8                    // n per CTA (fused kernels)
#define GRID_ 144                  // N_/NG_  (one full wave)

// u fp32, layout [n][ko][b]  (189 MB). v transposed [ko][b].
__device__ float g_u[(size_t)N_ * KO_ * B_];
__device__ float g_p[(size_t)GRID_ * KO_ * B_];   // cross-CTA partials (23.6 MB)
__device__ float g_vT[KO_ * B_];
__device__ float g_bij[N_ * C_];

__device__ __forceinline__ float dot8(float4 wa, float4 wb, float4 xa, float4 xb)
{
    return fmaf(wa.x, xa.x, fmaf(wa.y, xa.y, fmaf(wa.z, xa.z, fmaf(wa.w, xa.w,
           fmaf(wb.x, xb.x, fmaf(wb.y, xb.y, fmaf(wb.z, xb.z, wb.w * xb.w)))))));
}

// ---------------------------------------------------------------------------
// K1: u[n][ko][b] = sum_i W[n,ko,i]*x[b,n,i], fused s0-partial (= sum_n u).
// CTA = 8 n's, 512 thr = 64 b-quads x 8 ko-groups (ko = kg + 8j, j=0..19).
// ---------------------------------------------------------------------------
__global__ __launch_bounds__(512, 1) void uhat_s0(const float* __restrict__ x,
                                                  const float* __restrict__ W)
{
    __shared__ float4 Ws[KO_ * 2];           // W[n] as [ko][2 float4]
    const int t  = threadIdx.x;
    const int bq = t & 63, kg = t >> 6;
    const int b0 = bq * 4;

    float4 s0[20];
#pragma unroll
    for (int j = 0; j < 20; j++) s0[j] = make_float4(0.f, 0.f, 0.f, 0.f);

    for (int nn = 0; nn < NG_; nn++) {
        const int n = blockIdx.x * NG_ + nn;
        __syncthreads();                      // protect Ws reuse
        for (int j = t; j < KO_ * 2; j += 512)
            Ws[j] = ((const float4*)W)[(size_t)n * KO_ * 2 + j];
        __syncthreads();

        float4 xa[4], xb[4];
#pragma unroll
        for (int r = 0; r < 4; r++) {
            const float4* xp = (const float4*)(x + (size_t)(b0 + r) * (N_ * IN_) + n * IN_);
            xa[r] = __ldg(xp); xb[r] = __ldg(xp + 1);
        }
        float* up = g_u + (size_t)n * KO_ * B_ + b0;
#pragma unroll
        for (int j = 0; j < 20; j++) {
            const int ko = kg + 8 * j;
            const float4 wa = Ws[ko * 2], wb = Ws[ko * 2 + 1];
            float4 u;
            u.x = dot8(wa, wb, xa[0], xb[0]);
            u.y = dot8(wa, wb, xa[1], xb[1]);
            u.z = dot8(wa, wb, xa[2], xb[2]);
            u.w = dot8(wa, wb, xa[3], xb[3]);
            *(float4*)(up + (size_t)ko * B_) = u;           // 512B/warp store
            s0[j].x += u.x; s0[j].y += u.y; s0[j].z += u.z; s0[j].w += u.w;
        }
    }
    float* pp = g_p + (size_t)blockIdx.x * KO_ * B_ + b0;
#pragma unroll
    for (int j = 0; j < 20; j++)
        *(float4*)(pp + (size_t)(kg + 8 * j) * B_) = s0[j];
}

// ---------------------------------------------------------------------------
// K2: reduce partials over 144 CTAs, scale, squash; write v_T[ko][b]
//     (or final transposed output out[b][ko]).
// ---------------------------------------------------------------------------
__global__ __launch_bounds__(256) void reduce_sq(float scale, int final_out,
                                                 float* __restrict__ out)
{
    const int ko = blockIdx.x, b = threadIdx.x;
    const float* pp = g_p + (size_t)ko * B_ + b;
    float s = 0.f;
#pragma unroll 8
    for (int c = 0; c < GRID_; c++) s += pp[(size_t)c * (KO_ * B_)];
    s *= scale;
    const float v = s * fabsf(s) / (1.0f + s * s);
    if (final_out) out[b * KO_ + ko] = v;
    else           g_vT[ko * B_ + b] = v;
}

// ---------------------------------------------------------------------------
// K3: fused a-pass + next s-pass. CTA = 8 n's, 512 thr. v in smem (160KB).
// Per n: a[n,k] = (1/B) sum u*v -> bij update -> softmax -> c[n,:],
// then s-partial[j] += c * u (u reload hits L1/L2). Partials -> g_p.
// ---------------------------------------------------------------------------
extern __shared__ float vsm[];   // [KO_][B_]

__global__ __launch_bounds__(512, 1) void fused_as(int first)
{
    __shared__ float wred[16][C_];
    __shared__ float sb[C_];
    __shared__ float cs[C_];
    const int t  = threadIdx.x;
    const int bq = t & 63, kg = t >> 6;
    const int b0 = bq * 4;

    for (int j = t; j < KO_ * B_ / 4; j += 512)
        ((float4*)vsm)[j] = ((const float4*)g_vT)[j];
    __syncthreads();

    float4 sp[20];
#pragma unroll
    for (int j = 0; j < 20; j++) sp[j] = make_float4(0.f, 0.f, 0.f, 0.f);

    for (int nn = 0; nn < NG_; nn++) {
        const int n = blockIdx.x * NG_ + nn;
        const float* up = g_u + (size_t)n * KO_ * B_ + b0;

        float acc[C_];
#pragma unroll
        for (int k = 0; k < C_; k++) acc[k] = 0.f;
#pragma unroll
        for (int j = 0; j < 20; j++) {             // ko = kg+8j  ->  k = j>>1
            const int ko = kg + 8 * j;
            const float4 u = *(const float4*)(up + (size_t)ko * B_);
            const float4 v = *(const float4*)(vsm + ko * B_ + b0);
            acc[j >> 1] += fmaf(u.x, v.x, fmaf(u.y, v.y, fmaf(u.z, v.z, u.w * v.w)));
        }
#pragma unroll
        for (int k = 0; k < C_; k++) {
            float a = acc[k];
#pragma unroll
            for (int m = 16; m >= 1; m >>= 1)
                a += __shfl_xor_sync(0xffffffffu, a, m);
            if ((t & 31) == 0) wred[t >> 5][k] = a;
        }
        __syncthreads();
        if (t < C_) {
            float a = 0.f;
#pragma unroll
            for (int w = 0; w < 16; w++) a += wred[w][t];
            float bn = a * (1.0f / (float)B_);
            if (!first) bn += g_bij[n * C_ + t];
            g_bij[n * C_ + t] = bn;
            sb[t] = bn;
        }
        __syncthreads();
        if (t < C_) {
            float mx = -1e30f;
#pragma unroll
            for (int kk = 0; kk < C_; kk++) mx = fmaxf(mx, sb[kk]);
            float sum = 0.f;
#pragma unroll
            for (int kk = 0; kk < C_; kk++) sum += expf(sb[kk] - mx);
            cs[t] = expf(sb[t] - mx) / sum;
        }
        __syncthreads();
        // s-phase: reload u (L1/L2-resident), accumulate c * u
#pragma unroll
        for (int j = 0; j < 20; j++) {
            const int ko = kg + 8 * j;
            const float  c = cs[j >> 1];
            const float4 u = *(const float4*)(up + (size_t)ko * B_);
            sp[j].x = fmaf(c, u.x, sp[j].x);
            sp[j].y = fmaf(c, u.y, sp[j].y);
            sp[j].z = fmaf(c, u.z, sp[j].z);
            sp[j].w = fmaf(c, u.w, sp[j].w);
        }
        // no extra sync needed: next nn's wred writes are followed by a sync
        // before any thread reads them, and cs/sb rewrites sit behind 2 syncs.
    }
    float* pp = g_p + (size_t)blockIdx.x * KO_ * B_ + b0;
#pragma unroll
    for (int j = 0; j < 20; j++)
        *(float4*)(pp + (size_t)(kg + 8 * j) * B_) = sp[j];
}

// ---------------------------------------------------------------------------
extern "C" void kernel_launch(void* const* d_in, const int* in_sizes, int n_in,
                              void* d_out, int out_size)
{
    const float* x = (const float*)d_in[0];
    const float* W = (const float*)d_in[1];
    if (in_sizes[0] == N_ * C_ * 16 * IN_) { const float* t = x; x = W; W = t; }
    float* out = (float*)d_out;

    const int vbytes = KO_ * B_ * (int)sizeof(float);   // 160 KB dynamic smem
    cudaFuncSetAttribute(fused_as, cudaFuncAttributeMaxDynamicSharedMemorySize, vbytes);

    uhat_s0<<<GRID_, 512>>>(x, W);                 // write u + s0 partials
    reduce_sq<<<KO_, 256>>>(0.1f, 0, nullptr);     // v0 (c0 = 1/C)
    fused_as<<<GRID_, 512, vbytes>>>(1);           // a0 -> c1 -> s1 partials
    reduce_sq<<<KO_, 256>>>(1.0f, 0, nullptr);     // v1
    fused_as<<<GRID_, 512, vbytes>>>(0);           // a1 -> c2 -> s2 partials
    reduce_sq<<<KO_, 256>>>(1.0f, 1, out);         // v2 -> d_out [b][ko]
}

// round 6
// speedup vs baseline: 1.0069x; 1.0069x over previous
#include <cuda_runtime.h>
#include <math.h>

#define B_    256
#define N_    1152
#define C_    10
#define IN_   8
#define KO_   160
#define NG_   8                    // n per CTA (fused kernels)
#define GRID_ 144                  // N_/NG_  (one full wave)

// u fp32, layout [n][ko][b]  (189 MB). v transposed [ko][b].
__device__ float g_u[(size_t)N_ * KO_ * B_];
__device__ float g_p[(size_t)GRID_ * KO_ * B_];   // cross-CTA partials (23.6 MB)
__device__ float g_vT[KO_ * B_];
__device__ float g_bij[N_ * C_];

__device__ __forceinline__ float dot8(float4 wa, float4 wb, float4 xa, float4 xb)
{
    return fmaf(wa.x, xa.x, fmaf(wa.y, xa.y, fmaf(wa.z, xa.z, fmaf(wa.w, xa.w,
           fmaf(wb.x, xb.x, fmaf(wb.y, xb.y, fmaf(wb.z, xb.z, wb.w * xb.w)))))));
}

// ---------------------------------------------------------------------------
// K1: u[n][ko][b] = sum_i W[n,ko,i]*x[b,n,i], fused s0-partial (= sum_n u).
// CTA = 8 n's, 512 thr = 64 b-quads x 8 ko-groups (ko = kg + 8j, j=0..19).
// ---------------------------------------------------------------------------
__global__ __launch_bounds__(512, 1) void uhat_s0(const float* __restrict__ x,
                                                  const float* __restrict__ W)
{
    __shared__ float4 Ws[KO_ * 2];           // W[n] as [ko][2 float4]
    const int t  = threadIdx.x;
    const int bq = t & 63, kg = t >> 6;
    const int b0 = bq * 4;

    float4 s0[20];
#pragma unroll
    for (int j = 0; j < 20; j++) s0[j] = make_float4(0.f, 0.f, 0.f, 0.f);

    for (int nn = 0; nn < NG_; nn++) {
        const int n = blockIdx.x * NG_ + nn;
        __syncthreads();                      // protect Ws reuse
        for (int j = t; j < KO_ * 2; j += 512)
            Ws[j] = ((const float4*)W)[(size_t)n * KO_ * 2 + j];
        __syncthreads();

        float4 xa[4], xb[4];
#pragma unroll
        for (int r = 0; r < 4; r++) {
            const float4* xp = (const float4*)(x + (size_t)(b0 + r) * (N_ * IN_) + n * IN_);
            xa[r] = __ldg(xp); xb[r] = __ldg(xp + 1);
        }
        float* up = g_u + (size_t)n * KO_ * B_ + b0;
#pragma unroll
        for (int j = 0; j < 20; j++) {
            const int ko = kg + 8 * j;
            const float4 wa = Ws[ko * 2], wb = Ws[ko * 2 + 1];
            float4 u;
            u.x = dot8(wa, wb, xa[0], xb[0]);
            u.y = dot8(wa, wb, xa[1], xb[1]);
            u.z = dot8(wa, wb, xa[2], xb[2]);
            u.w = dot8(wa, wb, xa[3], xb[3]);
            *(float4*)(up + (size_t)ko * B_) = u;           // 512B/warp store
            s0[j].x += u.x; s0[j].y += u.y; s0[j].z += u.z; s0[j].w += u.w;
        }
    }
    float* pp = g_p + (size_t)blockIdx.x * KO_ * B_ + b0;
#pragma unroll
    for (int j = 0; j < 20; j++)
        *(float4*)(pp + (size_t)(kg + 8 * j) * B_) = s0[j];
}

// ---------------------------------------------------------------------------
// K2: reduce 144 partial slabs + scale + squash. One CTA per ko (grid 160),
// 256 thr = 64 b-quads x 4 slab-groups (36 slabs each), float4 loads.
// ---------------------------------------------------------------------------
__global__ __launch_bounds__(256) void reduce_sq(float scale, int final_out,
                                                 float* __restrict__ out)
{
    __shared__ float4 red[4][64];
    const int ko = blockIdx.x, t = threadIdx.x;
    const int bq = t & 63, cg = t >> 6;

    const float4* pp = (const float4*)(g_p + ((size_t)cg * KO_ + ko) * B_) + bq;
    const size_t str4 = (size_t)4 * KO_ * B_ / 4;   // 4 slabs, in float4

    float4 s = make_float4(0.f, 0.f, 0.f, 0.f);
#pragma unroll 9
    for (int j = 0; j < 36; j++) {
        float4 p = pp[(size_t)j * str4];
        s.x += p.x; s.y += p.y; s.z += p.z; s.w += p.w;
    }
    red[cg][bq] = s;
    __syncthreads();

    if (t < 64) {
        float4 a = red[0][t], b = red[1][t], c = red[2][t], d = red[3][t];
        float4 v;
        float sx = ((a.x + b.x) + (c.x + d.x)) * scale;
        float sy = ((a.y + b.y) + (c.y + d.y)) * scale;
        float sz = ((a.z + b.z) + (c.z + d.z)) * scale;
        float sw = ((a.w + b.w) + (c.w + d.w)) * scale;
        v.x = sx * fabsf(sx) / (1.0f + sx * sx);
        v.y = sy * fabsf(sy) / (1.0f + sy * sy);
        v.z = sz * fabsf(sz) / (1.0f + sz * sz);
        v.w = sw * fabsf(sw) / (1.0f + sw * sw);
        if (final_out) {
            out[(4 * t + 0) * KO_ + ko] = v.x;
            out[(4 * t + 1) * KO_ + ko] = v.y;
            out[(4 * t + 2) * KO_ + ko] = v.z;
            out[(4 * t + 3) * KO_ + ko] = v.w;
        } else {
            ((float4*)g_vT)[ko * 64 + t] = v;
        }
    }
}

// ---------------------------------------------------------------------------
// K3: fused a-pass + next s-pass, software-pipelined:
// warp 0 computes softmax(n) while all warps s-accumulate n-1 (cs double-buf).
// CTA = 8 n's, 512 thr; v in 160KB dynamic smem.
// ---------------------------------------------------------------------------
extern __shared__ float vsm[];   // [KO_][B_]

__global__ __launch_bounds__(512, 1) void fused_as(int first)
{
    __shared__ float wred[16][C_];
    __shared__ float csbuf[2][C_];
    const int t  = threadIdx.x;
    const int bq = t & 63, kg = t >> 6;
    const int b0 = bq * 4;
    const int wid = t >> 5, lane = t & 31;

    for (int j = t; j < KO_ * B_ / 4; j += 512)
        ((float4*)vsm)[j] = ((const float4*)g_vT)[j];
    __syncthreads();

    float4 sp[20];
#pragma unroll
    for (int j = 0; j < 20; j++) sp[j] = make_float4(0.f, 0.f, 0.f, 0.f);

    for (int nn = 0; nn < NG_; nn++) {
        const int n = blockIdx.x * NG_ + nn;
        const float* up = g_u + (size_t)n * KO_ * B_ + b0;

        // a-dot for n
        float acc[C_];
#pragma unroll
        for (int k = 0; k < C_; k++) acc[k] = 0.f;
#pragma unroll
        for (int j = 0; j < 20; j++) {
            const int ko = kg + 8 * j;
            const float4 u = *(const float4*)(up + (size_t)ko * B_);
            const float4 v = *(const float4*)(vsm + ko * B_ + b0);
            acc[j >> 1] += fmaf(u.x, v.x, fmaf(u.y, v.y, fmaf(u.z, v.z, u.w * v.w)));
        }
#pragma unroll
        for (int k = 0; k < C_; k++) {
            float a = acc[k];
#pragma unroll
            for (int m = 16; m >= 1; m >>= 1)
                a += __shfl_xor_sync(0xffffffffu, a, m);
            if (lane == 0) wred[wid][k] = a;
        }
        __syncthreads();   // publish wred(n); csbuf[(nn-1)&1] still live

        if (wid == 0) {
            // softmax(n) in one 16-lane butterfly (lanes >= C_ padded -inf/0)
            float bn = -1e30f;
            if (lane < C_) {
                float a = 0.f;
#pragma unroll
                for (int w = 0; w < 16; w++) a += wred[w][lane];
                bn = a * (1.0f / (float)B_);
                if (!first) bn += g_bij[n * C_ + lane];
                g_bij[n * C_ + lane] = bn;
            }
            if (lane < 16) {
                float mx = bn;
#pragma unroll
                for (int m = 8; m >= 1; m >>= 1)
                    mx = fmaxf(mx, __shfl_xor_sync(0x0000ffffu, mx, m, 16));
                float e = (lane < C_) ? expf(bn - mx) : 0.f;
                float sm = e;
#pragma unroll
                for (int m = 8; m >= 1; m >>= 1)
                    sm += __shfl_xor_sync(0x0000ffffu, sm, m, 16);
                if (lane < C_) csbuf[nn & 1][lane] = e / sm;
            }
        }
        // s-accumulate for n-1 (overlaps warp0's softmax)
        if (nn > 0) {
            const float* upm = g_u + (size_t)(n - 1) * KO_ * B_ + b0;
            const float* cp = csbuf[(nn - 1) & 1];
#pragma unroll
            for (int j = 0; j < 20; j++) {
                const int ko = kg + 8 * j;
                const float c = cp[j >> 1];
                const float4 u = *(const float4*)(upm + (size_t)ko * B_);
                sp[j].x = fmaf(c, u.x, sp[j].x);
                sp[j].y = fmaf(c, u.y, sp[j].y);
                sp[j].z = fmaf(c, u.z, sp[j].z);
                sp[j].w = fmaf(c, u.w, sp[j].w);
            }
        }
        __syncthreads();   // publish csbuf(n) before it's read at nn+1
    }
    // epilogue: s-accumulate for last n
    {
        const int n = blockIdx.x * NG_ + (NG_ - 1);
        const float* upm = g_u + (size_t)n * KO_ * B_ + b0;
        const float* cp = csbuf[(NG_ - 1) & 1];
#pragma unroll
        for (int j = 0; j < 20; j++) {
            const int ko = kg + 8 * j;
            const float c = cp[j >> 1];
            const float4 u = *(const float4*)(upm + (size_t)ko * B_);
            sp[j].x = fmaf(c, u.x, sp[j].x);
            sp[j].y = fmaf(c, u.y, sp[j].y);
            sp[j].z = fmaf(c, u.z, sp[j].z);
            sp[j].w = fmaf(c, u.w, sp[j].w);
        }
    }
    float* pp = g_p + (size_t)blockIdx.x * KO_ * B_ + b0;
#pragma unroll
    for (int j = 0; j < 20; j++)
        *(float4*)(pp + (size_t)(kg + 8 * j) * B_) = sp[j];
}

// ---------------------------------------------------------------------------
extern "C" void kernel_launch(void* const* d_in, const int* in_sizes, int n_in,
                              void* d_out, int out_size)
{
    const float* x = (const float*)d_in[0];
    const float* W = (const float*)d_in[1];
    if (in_sizes[0] == N_ * C_ * 16 * IN_) { const float* t = x; x = W; W = t; }
    float* out = (float*)d_out;

    const int vbytes = KO_ * B_ * (int)sizeof(float);   // 160 KB dynamic smem
    cudaFuncSetAttribute(fused_as, cudaFuncAttributeMaxDynamicSharedMemorySize, vbytes);

    uhat_s0<<<GRID_, 512>>>(x, W);                 // write u + s0 partials
    reduce_sq<<<KO_, 256>>>(0.1f, 0, nullptr);     // v0 (c0 = 1/C)
    fused_as<<<GRID_, 512, vbytes>>>(1);           // a0 -> c1 -> s1 partials
    reduce_sq<<<KO_, 256>>>(1.0f, 0, nullptr);     // v1
    fused_as<<<GRID_, 512, vbytes>>>(0);           // a1 -> c2 -> s2 partials
    reduce_sq<<<KO_, 256>>>(1.0f, 1, out);         // v2 -> d_out [b][ko]
}